// round 14
// baseline (speedup 1.0000x reference)
#include <cuda_runtime.h>
#include <cuda_bf16.h>
#include <math.h>

// Warp-specialized mma.sync bf16 hi/lo conv + min + softmax.
// CTA = (n,h), 512 threads: warps 0-7 pure MMA (A=x M=128px, B=weights N=24co
// persistent in regs), warps 8-15 pure im2col builders (px,part dest-owned,
// STS.128, granule swizzle). Ring-4 slices, 1 barrier/depth couples the roles.

typedef unsigned int u32;

#define XROW 64                          // 32 k * 2B (swizzled granules)
#define XPART (128 * XROW)               // 8192
#define XSLOT (2 * XPART)                // 16384 (hi+lo)
#define OFF_X 0
#define OFF_W (4 * XSLOT)                // 65536
#define WROW 64                          // 32 co * 2B
#define WPART (96 * WROW)                // 6144: [kd3][k32][co32]
#define SMEM_TOTAL (OFF_W + 2 * WPART + 64)   // 77888

__device__ __forceinline__ void ldsm4(u32* r, u32 a) {
    asm volatile("ldmatrix.sync.aligned.m8n8.x4.shared.b16 {%0,%1,%2,%3}, [%4];"
        : "=r"(r[0]), "=r"(r[1]), "=r"(r[2]), "=r"(r[3]) : "r"(a));
}
__device__ __forceinline__ void ldsm4t(u32* r, u32 a) {
    asm volatile("ldmatrix.sync.aligned.m8n8.x4.trans.shared.b16 {%0,%1,%2,%3}, [%4];"
        : "=r"(r[0]), "=r"(r[1]), "=r"(r[2]), "=r"(r[3]) : "r"(a));
}
__device__ __forceinline__ void ldsm2t(u32* r, u32 a) {
    asm volatile("ldmatrix.sync.aligned.m8n8.x2.trans.shared.b16 {%0,%1}, [%2];"
        : "=r"(r[0]), "=r"(r[1]) : "r"(a));
}
__device__ __forceinline__ void mma_bf16(float* d, const u32* a, u32 b0, u32 b1) {
    asm volatile(
        "mma.sync.aligned.m16n8k16.row.col.f32.bf16.bf16.f32 "
        "{%0,%1,%2,%3}, {%4,%5,%6,%7}, {%8,%9}, {%0,%1,%2,%3};"
        : "+f"(d[0]), "+f"(d[1]), "+f"(d[2]), "+f"(d[3])
        : "r"(a[0]), "r"(a[1]), "r"(a[2]), "r"(a[3]), "r"(b0), "r"(b1));
}
__device__ __forceinline__ void sts128(u32 a, u32 w0, u32 w1, u32 w2, u32 w3) {
    asm volatile("st.shared.v4.b32 [%0], {%1,%2,%3,%4};"
        :: "r"(a), "r"(w0), "r"(w1), "r"(w2), "r"(w3) : "memory");
}
__device__ __forceinline__ u32 cvt2(float fhi, float flo) {   // (bf16(fhi)<<16)|bf16(flo)
    u32 r;
    asm("cvt.rn.bf16x2.f32 %0, %1, %2;" : "=r"(r) : "f"(fhi), "f"(flo));
    return r;
}

extern "C" __global__ void __launch_bounds__(512, 1)
conv_mma_ws(const float* __restrict__ x, const float* __restrict__ wgt,
            const float* __restrict__ bias, float* __restrict__ out)
{
    extern __shared__ char sm[];
    const u32 sb = (u32)__cvta_generic_to_shared(sm);
    const int tid  = threadIdx.x;
    const int lane = tid & 31;
    const int wid  = tid >> 5;
    const bool is_mma = (wid < 8);
    const int h = blockIdx.x;
    const int n = blockIdx.y;

    // zero W pads
    for (int i = tid; i < 2 * WPART / 16; i += 512)
        *reinterpret_cast<float4*>(sm + OFF_W + i * 16) = make_float4(0.f, 0.f, 0.f, 0.f);
    __syncthreads();

    // ---- weights -> smem bf16 hi/lo: W[part][kd][k][co] ----
    for (int e = tid; e < 1944; e += 512) {
        int co = e / 81, tap = e % 81;
        int ci = tap / 27;
        int kd = (tap % 27) / 9;
        int kh = (tap % 9) / 3;
        int kw = tap % 3;
        float v = wgt[e];
        __nv_bfloat16 hb = __float2bfloat16(v);
        __nv_bfloat16 lb = __float2bfloat16(v - __bfloat162float(hb));
        int row = kd * 32 + (ci * 3 + kh) * 3 + kw;
        *reinterpret_cast<__nv_bfloat16*>(sm + OFF_W +         row * WROW + co * 2) = hb;
        *reinterpret_cast<__nv_bfloat16*>(sm + OFF_W + WPART + row * WROW + co * 2) = lb;
    }
    __syncthreads();

    // ============================ builder state ============================
    const int btid = tid - 256;            // 0..255 for builders
    const int bpx  = btid & 127;
    const int part = (btid >> 7) & 1;
    const int bsw  = (bpx >> 1) & 3;

    float pv[9];                            // kw=0 values of next slice
    auto build_ld = [&](int z) {            // builders only
        if (z >= 32) return;
        #pragma unroll
        for (int r9 = 0; r9 < 9; ++r9) {
            int ci = r9 / 3, kh = r9 % 3;
            pv[r9] = __ldg(x + ((size_t)((n * 3 + ci) * 32 + z) << 14)
                             + ((h + kh) << 7) + bpx);
        }
    };
    auto build_st = [&](int z, int slot) {  // builders only; consumes pv
        if (z >= 32) return;
        const u32 base = sb + OFF_X + (u32)(slot * XSLOT + part * XPART + bpx * 64);
        unsigned short hv[32];
        #pragma unroll
        for (int r9 = 0; r9 < 9; ++r9) {
            int ci = r9 / 3, kh = r9 % 3;
            const float* row = x + ((size_t)((n * 3 + ci) * 32 + z) << 14)
                                 + ((h + kh) << 7);
            int p1 = bpx + 1 < 128 ? bpx + 1 : 127;
            int p2 = bpx + 2 < 128 ? bpx + 2 : 127;
            float v0 = pv[r9];
            float v1 = __ldg(row + p1);      // L1 hit (line warmed by pv load)
            float v2 = __ldg(row + p2);
            #pragma unroll
            for (int kw = 0; kw < 3; ++kw) {
                float v = (kw == 0) ? v0 : (kw == 1 ? v1 : v2);
                u32 pw = cvt2(0.f, v);       // low half = bf16(v)
                if (part == 1) {
                    float hi = __uint_as_float(pw << 16);
                    pw = cvt2(0.f, v - hi);
                }
                hv[r9 * 3 + kw] = (unsigned short)(pw & 0xffffu);
            }
        }
        #pragma unroll
        for (int k = 27; k < 32; ++k) hv[k] = 0;
        #pragma unroll
        for (int g = 0; g < 4; ++g) {
            u32 w0 = (u32)hv[8*g]   | ((u32)hv[8*g+1] << 16);
            u32 w1 = (u32)hv[8*g+2] | ((u32)hv[8*g+3] << 16);
            u32 w2 = (u32)hv[8*g+4] | ((u32)hv[8*g+5] << 16);
            u32 w3 = (u32)hv[8*g+6] | ((u32)hv[8*g+7] << 16);
            sts128(base + (u32)((g ^ bsw) * 16), w0, w1, w2, w3);
        }
    };

    // ============================ MMA state ============================
    u32 Bh[3][2][6], Bl[3][2][6];
    const int pxr = wid * 16 + (lane & 15);           // MMA A-row (warps 0-7)
    const int c0  = lane >> 4;
    const int swr = (pxr >> 1) & 3;
    const u32 arow  = sb + OFF_X + (u32)(pxr * 64);
    const u32 offk0 = (u32)(((c0)     ^ swr) * 16);
    const u32 offk1 = (u32)(((2 + c0) ^ swr) * 16);

    // prologue: builders make slices 0-2 and preload pv(3); MMA warps load B-frags
    if (is_mma) {
        const u32 wb = sb + OFF_W;
        const int krow = lane & 15;
        const int coo  = (lane >> 4) * 8;
        #pragma unroll
        for (int kd = 0; kd < 3; ++kd)
            #pragma unroll
            for (int ks = 0; ks < 2; ++ks) {
                u32 rbase = (u32)((kd * 32 + ks * 16 + krow) * WROW);
                ldsm4t(Bh[kd][ks],     wb + rbase + (u32)(coo * 2));
                ldsm2t(Bh[kd][ks] + 4, wb + rbase + 32);
                ldsm4t(Bl[kd][ks],     wb + WPART + rbase + (u32)(coo * 2));
                ldsm2t(Bl[kd][ks] + 4, wb + WPART + rbase + 32);
            }
    } else {
        build_ld(0); build_st(0, 0);
        build_ld(1); build_st(1, 1);
        build_ld(2); build_st(2, 2);
        build_ld(3);                          // pipeline head
    }
    __syncthreads();

    const float INF = __int_as_float(0x7f800000);
    float mn[3][4];
    #pragma unroll
    for (int t = 0; t < 3; ++t)
        #pragma unroll
        for (int e = 0; e < 4; ++e) mn[t][e] = INF;

    #pragma unroll 1
    for (int d = 0; d < 30; ++d) {
        if (is_mma) {
            float D[3][4];
            #pragma unroll
            for (int t = 0; t < 3; ++t)
                #pragma unroll
                for (int e = 0; e < 4; ++e) D[t][e] = 0.f;

            #pragma unroll
            for (int kd = 0; kd < 3; ++kd) {
                const u32 sa = arow + (u32)(((d + kd) & 3) * XSLOT);
                #pragma unroll
                for (int ks = 0; ks < 2; ++ks) {
                    const u32 off = ks ? offk1 : offk0;
                    u32 Ah[4], Al[4];
                    ldsm4(Ah, sa + off);
                    ldsm4(Al, sa + (u32)XPART + off);
                    #pragma unroll
                    for (int nt = 0; nt < 3; ++nt) {
                        mma_bf16(D[nt], Ah, Bh[kd][ks][2*nt], Bh[kd][ks][2*nt+1]);
                        mma_bf16(D[nt], Al, Bh[kd][ks][2*nt], Bh[kd][ks][2*nt+1]);
                        mma_bf16(D[nt], Ah, Bl[kd][ks][2*nt], Bl[kd][ks][2*nt+1]);
                    }
                }
            }
            #pragma unroll
            for (int t = 0; t < 3; ++t)
                #pragma unroll
                for (int e = 0; e < 4; ++e) mn[t][e] = fminf(mn[t][e], D[t][e]);
        } else {
            build_st(d + 3, (d + 3) & 3);    // concurrent with MMA(d)
            build_ld(d + 4);                  // prefetch next slice's pv
        }
        __syncthreads();                      // publish slice d+3; retire slot d&3
    }

    // ---- scatter min to sf[px128][28], bias + softmax ----
    float* sf = reinterpret_cast<float*>(sm);  // aliases X (all reads done)
    if (is_mma) {
        const int r0 = wid * 16 + (lane >> 2);
        const int cs = (lane & 3) * 2;
        #pragma unroll
        for (int nt = 0; nt < 3; ++nt) {
            sf[r0 * 28 + nt * 8 + cs]           = mn[nt][0];
            sf[r0 * 28 + nt * 8 + cs + 1]       = mn[nt][1];
            sf[(r0 + 8) * 28 + nt * 8 + cs]     = mn[nt][2];
            sf[(r0 + 8) * 28 + nt * 8 + cs + 1] = mn[nt][3];
        }
    }
    __syncthreads();

    if (tid < 126) {
        float v[24];
        float m = -INF;
        #pragma unroll
        for (int c = 0; c < 24; ++c) {
            v[c] = sf[tid * 28 + c] + __ldg(&bias[c]);
            m = fmaxf(m, v[c]);
        }
        float s = 0.f;
        #pragma unroll
        for (int c = 0; c < 24; ++c) { v[c] = __expf(v[c] - m); s += v[c]; }
        const float inv = 1.0f / s;
        float* op = out + (size_t)n * 24 * 15876 + (size_t)h * 126 + tid;
        #pragma unroll
        for (int c = 0; c < 24; ++c)
            op[(size_t)c * 15876] = v[c] * inv;
    }
}

extern "C" void kernel_launch(void* const* d_in, const int* in_sizes, int n_in,
                              void* d_out, int out_size) {
    const float* x    = (const float*)d_in[0];
    const float* wgt  = (const float*)d_in[1];
    const float* bias = (const float*)d_in[2];
    float* out        = (float*)d_out;

    cudaFuncSetAttribute(conv_mma_ws,
                         cudaFuncAttributeMaxDynamicSharedMemorySize, SMEM_TOTAL);

    dim3 grid(126, 16);   // (h, n)
    conv_mma_ws<<<grid, 512, SMEM_TOTAL>>>(x, wgt, bias, out);
}

// round 15
// speedup vs baseline: 1.2987x; 1.2987x over previous
#include <cuda_runtime.h>
#include <cuda_bf16.h>
#include <math.h>

// mma.sync bf16 hi/lo split, A = x (M=px128), B = weights (N=co24, persistent regs).
// Build v3: LDG fetch (R12) + pairwise cvt.rn.bf16x2 conversions (R13), no shuffle.
// 4x STS.128 per thread, XROW=64 granule swizzle. Ring-4, 1 sync/depth, occ 2.

typedef unsigned int u32;

#define XROW 64                          // 32 k * 2B, no pad (swizzled)
#define XPART (128 * XROW)               // 8192
#define XSLOT (2 * XPART)                // 16384 (hi+lo)
#define OFF_X 0
#define OFF_W (4 * XSLOT)                // 65536
#define WROW 64                          // 32 co * 2B
#define WPART (96 * WROW)                // 6144: [kd3][k32][co32]
#define SMEM_TOTAL (OFF_W + 2 * WPART + 64)   // 77888

__device__ __forceinline__ void ldsm4(u32* r, u32 a) {
    asm volatile("ldmatrix.sync.aligned.m8n8.x4.shared.b16 {%0,%1,%2,%3}, [%4];"
        : "=r"(r[0]), "=r"(r[1]), "=r"(r[2]), "=r"(r[3]) : "r"(a));
}
__device__ __forceinline__ void ldsm4t(u32* r, u32 a) {
    asm volatile("ldmatrix.sync.aligned.m8n8.x4.trans.shared.b16 {%0,%1,%2,%3}, [%4];"
        : "=r"(r[0]), "=r"(r[1]), "=r"(r[2]), "=r"(r[3]) : "r"(a));
}
__device__ __forceinline__ void ldsm2t(u32* r, u32 a) {
    asm volatile("ldmatrix.sync.aligned.m8n8.x2.trans.shared.b16 {%0,%1}, [%2];"
        : "=r"(r[0]), "=r"(r[1]) : "r"(a));
}
__device__ __forceinline__ void mma_bf16(float* d, const u32* a, u32 b0, u32 b1) {
    asm volatile(
        "mma.sync.aligned.m16n8k16.row.col.f32.bf16.bf16.f32 "
        "{%0,%1,%2,%3}, {%4,%5,%6,%7}, {%8,%9}, {%0,%1,%2,%3};"
        : "+f"(d[0]), "+f"(d[1]), "+f"(d[2]), "+f"(d[3])
        : "r"(a[0]), "r"(a[1]), "r"(a[2]), "r"(a[3]), "r"(b0), "r"(b1));
}
__device__ __forceinline__ void sts128(u32 a, u32 w0, u32 w1, u32 w2, u32 w3) {
    asm volatile("st.shared.v4.b32 [%0], {%1,%2,%3,%4};"
        :: "r"(a), "r"(w0), "r"(w1), "r"(w2), "r"(w3) : "memory");
}
__device__ __forceinline__ u32 cvt2(float fhi, float flo) {   // (bf16(fhi)<<16)|bf16(flo)
    u32 r;
    asm("cvt.rn.bf16x2.f32 %0, %1, %2;" : "=r"(r) : "f"(fhi), "f"(flo));
    return r;
}

extern "C" __global__ void __launch_bounds__(256, 2)
conv_mma(const float* __restrict__ x, const float* __restrict__ wgt,
         const float* __restrict__ bias, float* __restrict__ out)
{
    extern __shared__ char sm[];
    const u32 sb = (u32)__cvta_generic_to_shared(sm);
    const int tid  = threadIdx.x;
    const int lane = tid & 31;
    const int wid  = tid >> 5;
    const int h = blockIdx.x;
    const int n = blockIdx.y;

    // zero W region (co/k pads); X fully overwritten each build
    for (int i = tid; i < 2 * WPART / 16; i += 256)
        *reinterpret_cast<float4*>(sm + OFF_W + i * 16) = make_float4(0.f, 0.f, 0.f, 0.f);
    __syncthreads();

    // ---- weights -> smem bf16 hi/lo: W[part][kd][k][co], k=(ci*3+kh)*3+kw ----
    for (int e = tid; e < 1944; e += 256) {
        int co = e / 81, tap = e % 81;
        int ci = tap / 27;
        int kd = (tap % 27) / 9;
        int kh = (tap % 9) / 3;
        int kw = tap % 3;
        float v = wgt[e];
        __nv_bfloat16 hb = __float2bfloat16(v);
        __nv_bfloat16 lb = __float2bfloat16(v - __bfloat162float(hb));
        int row = kd * 32 + (ci * 3 + kh) * 3 + kw;
        *reinterpret_cast<__nv_bfloat16*>(sm + OFF_W +         row * WROW + co * 2) = hb;
        *reinterpret_cast<__nv_bfloat16*>(sm + OFF_W + WPART + row * WROW + co * 2) = lb;
    }

    // ---- dest-owned build: thread = (px, part) ----
    const int bpx  = tid & 127;
    const int part = tid >> 7;
    const int bsw  = (bpx >> 1) & 3;

    float pv[9];                                 // kw=0 values (prefetched)
    auto build_ld = [&](int z) {
        if (z >= 32) return;
        #pragma unroll
        for (int r9 = 0; r9 < 9; ++r9) {
            int ci = r9 / 3, kh = r9 % 3;
            pv[r9] = __ldg(x + ((size_t)((n * 3 + ci) * 32 + z) << 14)
                             + ((h + kh) << 7) + bpx);
        }
    };

    // row r9 -> 3 values: v0 from pv, v1/v2 via L1-hit LDG (line warmed by pv)
    auto fetchrow = [&](int r9, int z, float* dst) {
        int ci = r9 / 3, kh = r9 % 3;
        const float* row = x + ((size_t)((n * 3 + ci) * 32 + z) << 14)
                             + ((h + kh) << 7);
        dst[0] = pv[r9];
        dst[1] = __ldg(row + (bpx + 1 < 128 ? bpx + 1 : 127));
        dst[2] = __ldg(row + (bpx + 2 < 128 ? bpx + 2 : 127));
    };

    // pack (flo, fhi) -> word; part0 = hi bf16s, part1 = lo residual bf16s
    auto cvtpair = [&](float flo, float fhi) -> u32 {
        u32 hw = cvt2(fhi, flo);
        if (part == 0) return hw;
        float hlo = __uint_as_float(hw << 16);
        float hhi = __uint_as_float(hw & 0xffff0000u);
        return cvt2(fhi - hhi, flo - hlo);
    };

    auto build_st = [&](int z, int slot) {
        if (z >= 32) return;
        const u32 base = sb + OFF_X + (u32)(slot * XSLOT + part * XPART + bpx * 64);
        u32 w[16];
        float va[6];
        #pragma unroll
        for (int rr = 0; rr < 4; ++rr) {         // rows (2rr, 2rr+1) -> k 6rr..6rr+5
            fetchrow(rr * 2,     z, va);
            fetchrow(rr * 2 + 1, z, va + 3);
            w[rr * 3 + 0] = cvtpair(va[0], va[1]);
            w[rr * 3 + 1] = cvtpair(va[2], va[3]);
            w[rr * 3 + 2] = cvtpair(va[4], va[5]);
        }
        fetchrow(8, z, va);                      // k 24..26 (+pad)
        w[12] = cvtpair(va[0], va[1]);
        w[13] = cvtpair(va[2], 0.f);
        w[14] = 0; w[15] = 0;
        #pragma unroll
        for (int g = 0; g < 4; ++g)
            sts128(base + (u32)((g ^ bsw) * 16), w[4*g], w[4*g+1], w[4*g+2], w[4*g+3]);
    };

    build_ld(0); build_st(0, 0);
    build_ld(1); build_st(1, 1);
    build_ld(2); build_st(2, 2);
    __syncthreads();

    // ---- persistent weight B-fragments ----
    u32 Bh[3][2][6], Bl[3][2][6];
    {
        const u32 wb = sb + OFF_W;
        const int krow = lane & 15;
        const int coo  = (lane >> 4) * 8;
        #pragma unroll
        for (int kd = 0; kd < 3; ++kd)
            #pragma unroll
            for (int ks = 0; ks < 2; ++ks) {
                u32 rbase = (u32)((kd * 32 + ks * 16 + krow) * WROW);
                ldsm4t(Bh[kd][ks],     wb + rbase + (u32)(coo * 2));
                ldsm2t(Bh[kd][ks] + 4, wb + rbase + 32);
                ldsm4t(Bl[kd][ks],     wb + WPART + rbase + (u32)(coo * 2));
                ldsm2t(Bl[kd][ks] + 4, wb + WPART + rbase + 32);
            }
    }

    // A-frag lane addressing (swizzled)
    const int pxr = wid * 16 + (lane & 15);
    const int c0  = lane >> 4;
    const int swr = (pxr >> 1) & 3;
    const u32 arow  = sb + OFF_X + (u32)(pxr * 64);
    const u32 offk0 = (u32)(((c0)     ^ swr) * 16);
    const u32 offk1 = (u32)(((2 + c0) ^ swr) * 16);

    const float INF = __int_as_float(0x7f800000);
    float mn[3][4];
    #pragma unroll
    for (int t = 0; t < 3; ++t)
        #pragma unroll
        for (int e = 0; e < 4; ++e) mn[t][e] = INF;

    #pragma unroll 1
    for (int d = 0; d < 30; ++d) {
        build_ld(d + 3);                 // DRAM prefetch into regs

        float D[3][4];
        #pragma unroll
        for (int t = 0; t < 3; ++t)
            #pragma unroll
            for (int e = 0; e < 4; ++e) D[t][e] = 0.f;

        #pragma unroll
        for (int kd = 0; kd < 3; ++kd) {
            const u32 sa = arow + (u32)(((d + kd) & 3) * XSLOT);
            #pragma unroll
            for (int ks = 0; ks < 2; ++ks) {
                const u32 off = ks ? offk1 : offk0;
                u32 Ah[4], Al[4];
                ldsm4(Ah, sa + off);
                ldsm4(Al, sa + (u32)XPART + off);
                #pragma unroll
                for (int nt = 0; nt < 3; ++nt) {
                    mma_bf16(D[nt], Ah, Bh[kd][ks][2*nt], Bh[kd][ks][2*nt+1]); // hh
                    mma_bf16(D[nt], Al, Bh[kd][ks][2*nt], Bh[kd][ks][2*nt+1]); // lh
                    mma_bf16(D[nt], Ah, Bl[kd][ks][2*nt], Bl[kd][ks][2*nt+1]); // hl
                }
            }
        }

        #pragma unroll
        for (int t = 0; t < 3; ++t)
            #pragma unroll
            for (int e = 0; e < 4; ++e) mn[t][e] = fminf(mn[t][e], D[t][e]);

        build_st(d + 3, (d + 3) & 3);
        __syncthreads();
    }

    // ---- scatter min to sf[px128][28], bias + softmax ----
    float* sf = reinterpret_cast<float*>(sm);    // aliases X (reads done)
    {
        const int r0 = wid * 16 + (lane >> 2);
        const int cs = (lane & 3) * 2;
        #pragma unroll
        for (int nt = 0; nt < 3; ++nt) {
            sf[r0 * 28 + nt * 8 + cs]           = mn[nt][0];
            sf[r0 * 28 + nt * 8 + cs + 1]       = mn[nt][1];
            sf[(r0 + 8) * 28 + nt * 8 + cs]     = mn[nt][2];
            sf[(r0 + 8) * 28 + nt * 8 + cs + 1] = mn[nt][3];
        }
    }
    __syncthreads();

    if (tid < 126) {
        float v[24];
        float m = -INF;
        #pragma unroll
        for (int c = 0; c < 24; ++c) {
            v[c] = sf[tid * 28 + c] + __ldg(&bias[c]);
            m = fmaxf(m, v[c]);
        }
        float s = 0.f;
        #pragma unroll
        for (int c = 0; c < 24; ++c) { v[c] = __expf(v[c] - m); s += v[c]; }
        const float inv = 1.0f / s;
        float* op = out + (size_t)n * 24 * 15876 + (size_t)h * 126 + tid;
        #pragma unroll
        for (int c = 0; c < 24; ++c)
            op[(size_t)c * 15876] = v[c] * inv;
    }
}

extern "C" void kernel_launch(void* const* d_in, const int* in_sizes, int n_in,
                              void* d_out, int out_size) {
    const float* x    = (const float*)d_in[0];
    const float* wgt  = (const float*)d_in[1];
    const float* bias = (const float*)d_in[2];
    float* out        = (float*)d_out;

    cudaFuncSetAttribute(conv_mma,
                         cudaFuncAttributeMaxDynamicSharedMemorySize, SMEM_TOTAL);

    dim3 grid(126, 16);   // (h, n)
    conv_mma<<<grid, 256, SMEM_TOTAL>>>(x, wgt, bias, out);
}